// round 2
// baseline (speedup 1.0000x reference)
#include <cuda_runtime.h>
#include <math.h>
#include <stdint.h>

// Problem dims
#define I_IMG 32
#define C_CAP 32
#define Q_RGN 36
#define L_MAX 50
#define D_EMB 1024
#define M_TOT (C_CAP * I_IMG * Q_RGN)          // 36864
#define ELEMS ((size_t)M_TOT * D_EMB)          // 37,748,736

// Scratch (static device globals — allocation-free per harness rules)
__device__ float g_wei[ELEMS];
__device__ float g_bufA[ELEMS];
__device__ float g_bufB[ELEMS];

// ---------------------------------------------------------------------------
// K1: per-(c,i) fused  scores -> leaky -> L2norm(q) -> masked softmax(l) -> wei
// grid = (I_IMG, C_CAP), block = 256
// ---------------------------------------------------------------------------
__global__ __launch_bounds__(256) void attn_wei_kernel(
    const float* __restrict__ rgn, const float* __restrict__ wrd,
    const int* __restrict__ lens, float* __restrict__ wei)
{
    const int i = blockIdx.x;
    const int c = blockIdx.y;
    const int tid = threadIdx.x;

    __shared__ float sW[L_MAX][33];        // wrd d-chunk
    __shared__ float sR[Q_RGN][33];        // rgn d-chunk
    __shared__ float sS[L_MAX][Q_RGN + 1]; // scores / attn

    const float* wrdC = wrd + (size_t)c * L_MAX * D_EMB;
    const float* rgnI = rgn + (size_t)i * Q_RGN * D_EMB;

    float acc[8];
    int pl[8], pq[8];
#pragma unroll
    for (int j = 0; j < 8; j++) {
        acc[j] = 0.f;
        int p = tid + 256 * j;
        pl[j] = p / Q_RGN;
        pq[j] = p - pl[j] * Q_RGN;
    }

    // Stage 1: s[l][q] = wrd[c,l,:] . rgn[i,q,:]  (d tiled by 32)
    for (int d0 = 0; d0 < D_EMB; d0 += 32) {
        __syncthreads();
        for (int f = tid; f < L_MAX * 32; f += 256) {
            int r = f >> 5, dd = f & 31;
            sW[r][dd] = wrdC[r * D_EMB + d0 + dd];
        }
        for (int f = tid; f < Q_RGN * 32; f += 256) {
            int r = f >> 5, dd = f & 31;
            sR[r][dd] = rgnI[r * D_EMB + d0 + dd];
        }
        __syncthreads();
#pragma unroll
        for (int j = 0; j < 8; j++) {
            if (pl[j] < L_MAX) {
                float a = 0.f;
#pragma unroll
                for (int dd = 0; dd < 32; dd++)
                    a += sW[pl[j]][dd] * sR[pq[j]][dd];
                acc[j] += a;
            }
        }
    }
    __syncthreads();

    // LeakyReLU(0.1) and store to smem
#pragma unroll
    for (int j = 0; j < 8; j++) {
        if (pl[j] < L_MAX) {
            float v = acc[j];
            sS[pl[j]][pq[j]] = (v >= 0.f) ? v : 0.1f * v;
        }
    }
    __syncthreads();

    // L2-normalize each l-row over q
    if (tid < L_MAX) {
        float ss = 0.f;
        for (int q = 0; q < Q_RGN; q++) { float v = sS[tid][q]; ss += v * v; }
        float inv = 1.f / fmaxf(sqrtf(ss), 1e-12f);
        for (int q = 0; q < Q_RGN; q++) sS[tid][q] *= inv;
    }
    __syncthreads();

    const int len = lens[c];

    // Masked softmax over l (temperature 9), per q column; overwrite sS w/ attn
    if (tid < Q_RGN) {
        float mx = -1e30f;
        for (int l = 0; l < len; l++) mx = fmaxf(mx, sS[l][tid]);
        float sum = 0.f;
        for (int l = 0; l < len; l++) sum += expf(9.f * (sS[l][tid] - mx));
        float invs = 1.f / sum;
        for (int l = 0; l < L_MAX; l++) {
            float a = (l < len) ? expf(9.f * (sS[l][tid] - mx)) * invs : 0.f;
            sS[l][tid] = a;
        }
    }
    __syncthreads();

    // Stage 3: wei[c,i,q,d] = sum_{l<len} attn[l][q] * wrd[c,l,d]
    float* weiOut = wei + ((size_t)(c * I_IMG + i)) * Q_RGN * D_EMB;
    for (int q = 0; q < Q_RGN; q++) {
        for (int d = tid; d < D_EMB; d += 256) {
            float a = 0.f;
            for (int l = 0; l < len; l++)
                a += sS[l][q] * wrdC[l * D_EMB + d];
            weiOut[q * D_EMB + d] = a;
        }
    }
}

// ---------------------------------------------------------------------------
// GEMM: out[m,n] = epi( sum_k A[m,k]*W[n,k] + bias[n] )   M=36864,N=K=1024
// 128x128 tile, BK=8, 8x8 per-thread tile, 256 threads.
// ---------------------------------------------------------------------------
#define EPI_TANH 0
#define EPI_LINEAR 1
#define EPI_RELU 2
#define EPI_FINAL 3

template <int EPI>
__global__ __launch_bounds__(256) void gemm1024_kernel(
    const float* __restrict__ A, const float* __restrict__ W,
    const float* __restrict__ bias, const float* __restrict__ rgn,
    float* __restrict__ out)
{
    constexpr int K = D_EMB;
    __shared__ float As[8][128];
    __shared__ float Bs[8][128];

    const int tid = threadIdx.x;
    const int m0 = blockIdx.y * 128;
    const int n0 = blockIdx.x * 128;
    const int lr = tid >> 1;         // 0..127
    const int lc = (tid & 1) * 4;    // 0 or 4
    const int ty = tid >> 4;         // 0..15
    const int tx = tid & 15;         // 0..15

    const float* Aptr = A + (size_t)(m0 + lr) * K + lc;
    const float* Wptr = W + (size_t)(n0 + lr) * K + lc;

    float acc[8][8];
#pragma unroll
    for (int a = 0; a < 8; a++)
#pragma unroll
        for (int b = 0; b < 8; b++) acc[a][b] = 0.f;

    for (int kk = 0; kk < K; kk += 8) {
        float4 av = *(const float4*)(Aptr + kk);
        float4 wv = *(const float4*)(Wptr + kk);
        __syncthreads();
        As[lc + 0][lr] = av.x; As[lc + 1][lr] = av.y;
        As[lc + 2][lr] = av.z; As[lc + 3][lr] = av.w;
        Bs[lc + 0][lr] = wv.x; Bs[lc + 1][lr] = wv.y;
        Bs[lc + 2][lr] = wv.z; Bs[lc + 3][lr] = wv.w;
        __syncthreads();
#pragma unroll
        for (int k = 0; k < 8; k++) {
            float a[8], b[8];
#pragma unroll
            for (int j = 0; j < 8; j++) a[j] = As[k][ty * 8 + j];
#pragma unroll
            for (int j = 0; j < 8; j++) b[j] = Bs[k][tx * 8 + j];
#pragma unroll
            for (int ii = 0; ii < 8; ii++)
#pragma unroll
                for (int jj = 0; jj < 8; jj++)
                    acc[ii][jj] += a[ii] * b[jj];
        }
    }

    float bv[8];
#pragma unroll
    for (int j = 0; j < 8; j++) bv[j] = bias[n0 + tx * 8 + j];

#pragma unroll
    for (int ii = 0; ii < 8; ii++) {
        int m = m0 + ty * 8 + ii;
        if (EPI == EPI_FINAL) {
            int q = m % Q_RGN;
            int t = m / Q_RGN;
            int ii_img = t & (I_IMG - 1);
            int cc = t >> 5;   // / I_IMG
            size_t ob = (((size_t)ii_img * C_CAP + cc) * Q_RGN + q) * D_EMB + n0 + tx * 8;
            const float* rg = rgn + ((size_t)ii_img * Q_RGN + q) * D_EMB + n0 + tx * 8;
#pragma unroll
            for (int jj = 0; jj < 8; jj++)
                out[ob + jj] = acc[ii][jj] + bv[jj] + rg[jj];
        } else {
            size_t ob = (size_t)m * D_EMB + n0 + tx * 8;
#pragma unroll
            for (int jj = 0; jj < 8; jj++) {
                float v = acc[ii][jj] + bv[jj];
                if (EPI == EPI_TANH) v = tanhf(v);
                if (EPI == EPI_RELU) v = fmaxf(v, 0.f);
                out[ob + jj] = v;
            }
        }
    }
}

// ---------------------------------------------------------------------------
// K4: FiLM elementwise  x = rgn * scaling + shifting   (float4)
// ---------------------------------------------------------------------------
__global__ __launch_bounds__(256) void film_kernel(
    const float* __restrict__ scaling, const float* __restrict__ shifting,
    const float* __restrict__ rgn, float* __restrict__ x)
{
    int idx = blockIdx.x * blockDim.x + threadIdx.x;   // float4 index
    const int total4 = (int)(ELEMS / 4);               // 9,437,184
    if (idx >= total4) return;
    float4 sc = ((const float4*)scaling)[idx];
    float4 sh = ((const float4*)shifting)[idx];
    int d4 = idx & 255;            // D/4 = 256
    int m = idx >> 8;
    int q = m % Q_RGN;
    int t = m / Q_RGN;
    int i_img = t & (I_IMG - 1);
    float4 rg = ((const float4*)rgn)[(i_img * Q_RGN + q) * 256 + d4];
    float4 o;
    o.x = rg.x * sc.x + sh.x;
    o.y = rg.y * sc.y + sh.y;
    o.z = rg.z * sc.z + sh.z;
    o.w = rg.w * sc.w + sh.w;
    ((float4*)x)[idx] = o;
}

// ---------------------------------------------------------------------------
extern "C" void kernel_launch(void* const* d_in, const int* in_sizes, int n_in,
                              void* d_out, int out_size)
{
    const float* rgn     = (const float*)d_in[0];
    // d_in[1] = img (unused), d_in[3] = stc (unused)
    const float* wrd     = (const float*)d_in[2];
    const int*   lens    = (const int*)d_in[4];
    const float* w_scale = (const float*)d_in[5];
    const float* b_scale = (const float*)d_in[6];
    const float* w_shift = (const float*)d_in[7];
    const float* b_shift = (const float*)d_in[8];
    const float* w1      = (const float*)d_in[9];
    const float* b1      = (const float*)d_in[10];
    const float* w2      = (const float*)d_in[11];
    const float* b2      = (const float*)d_in[12];
    float* out = (float*)d_out;

    float *wei, *bufA, *bufB;
    cudaGetSymbolAddress((void**)&wei,  g_wei);
    cudaGetSymbolAddress((void**)&bufA, g_bufA);
    cudaGetSymbolAddress((void**)&bufB, g_bufB);

    // K1: attention + weighted context
    attn_wei_kernel<<<dim3(I_IMG, C_CAP), 256>>>(rgn, wrd, lens, wei);

    dim3 ggrid(D_EMB / 128, M_TOT / 128);   // (8, 288)

    // K2: scaling = tanh(wei @ w_scale^T + b_scale)  -> bufA
    gemm1024_kernel<EPI_TANH><<<ggrid, 256>>>(wei, w_scale, b_scale, nullptr, bufA);
    // K3: shifting = wei @ w_shift^T + b_shift       -> bufB
    gemm1024_kernel<EPI_LINEAR><<<ggrid, 256>>>(wei, w_shift, b_shift, nullptr, bufB);
    // K4: x = rgn * scaling + shifting               -> wei (reuse)
    film_kernel<<<(int)(ELEMS / 4 / 256), 256>>>(bufA, bufB, rgn, wei);
    // K5: h = relu(x @ w1^T + b1)                    -> bufA
    gemm1024_kernel<EPI_RELU><<<ggrid, 256>>>(wei, w1, b1, nullptr, bufA);
    // K6: out = (h @ w2^T + b2) + rgn, transposed (C,I)->(I,C)
    gemm1024_kernel<EPI_FINAL><<<ggrid, 256>>>(bufA, w2, b2, rgn, out);
}

// round 5
// speedup vs baseline: 2.3492x; 2.3492x over previous
#include <cuda_runtime.h>
#include <cuda_fp16.h>
#include <math.h>
#include <stdint.h>

// Problem dims
#define I_IMG 32
#define C_CAP 32
#define Q_RGN 36
#define L_MAX 50
#define D_EMB 1024
#define M_TOT (C_CAP * I_IMG * Q_RGN)          // 36864
#define ELEMS ((size_t)M_TOT * D_EMB)          // 37,748,736
#define W_ELEMS (D_EMB * D_EMB)

// ---------------- scratch (device globals; allocation-free) ----------------
__device__ __align__(256) __half g_weiH[ELEMS];
__device__ __align__(256) __half g_weiL[ELEMS];
__device__ __align__(256) __half g_xH[ELEMS];
__device__ __align__(256) __half g_xL[ELEMS];
__device__ __align__(256) __half g_hH[ELEMS];
__device__ __align__(256) __half g_hL[ELEMS];
__device__ __align__(256) float  g_scal[ELEMS];
__device__ __align__(256) __half g_wH[4][W_ELEMS];
__device__ __align__(256) __half g_wL[4][W_ELEMS];

__device__ __forceinline__ void split_h(float x, __half& h, __half& l) {
    h = __float2half_rn(x);
    l = __float2half_rn(x - __half2float(h));
}

// ---------------------------------------------------------------------------
// K1: per-(c,i) fused attention -> wei (fp16 hi/lo output)
// ---------------------------------------------------------------------------
__global__ __launch_bounds__(256) void attn_wei_kernel(
    const float* __restrict__ rgn, const float* __restrict__ wrd,
    const int* __restrict__ lens,
    __half* __restrict__ weiH, __half* __restrict__ weiL)
{
    const int i = blockIdx.x;
    const int c = blockIdx.y;
    const int tid = threadIdx.x;

    __shared__ float sW[L_MAX][33];
    __shared__ float sR[Q_RGN][33];
    __shared__ float sS[L_MAX][Q_RGN + 1];

    const float* wrdC = wrd + (size_t)c * L_MAX * D_EMB;
    const float* rgnI = rgn + (size_t)i * Q_RGN * D_EMB;

    float acc[8];
    int pl[8], pq[8];
#pragma unroll
    for (int j = 0; j < 8; j++) {
        acc[j] = 0.f;
        int p = tid + 256 * j;
        pl[j] = p / Q_RGN;
        pq[j] = p - pl[j] * Q_RGN;
    }

    for (int d0 = 0; d0 < D_EMB; d0 += 32) {
        __syncthreads();
        for (int f = tid; f < L_MAX * 32; f += 256) {
            int r = f >> 5, dd = f & 31;
            sW[r][dd] = wrdC[r * D_EMB + d0 + dd];
        }
        for (int f = tid; f < Q_RGN * 32; f += 256) {
            int r = f >> 5, dd = f & 31;
            sR[r][dd] = rgnI[r * D_EMB + d0 + dd];
        }
        __syncthreads();
#pragma unroll
        for (int j = 0; j < 8; j++) {
            if (pl[j] < L_MAX) {
                float a = 0.f;
#pragma unroll
                for (int dd = 0; dd < 32; dd++)
                    a += sW[pl[j]][dd] * sR[pq[j]][dd];
                acc[j] += a;
            }
        }
    }
    __syncthreads();

#pragma unroll
    for (int j = 0; j < 8; j++) {
        if (pl[j] < L_MAX) {
            float v = acc[j];
            sS[pl[j]][pq[j]] = (v >= 0.f) ? v : 0.1f * v;
        }
    }
    __syncthreads();

    if (tid < L_MAX) {
        float ss = 0.f;
        for (int q = 0; q < Q_RGN; q++) { float v = sS[tid][q]; ss += v * v; }
        float inv = 1.f / fmaxf(sqrtf(ss), 1e-12f);
        for (int q = 0; q < Q_RGN; q++) sS[tid][q] *= inv;
    }
    __syncthreads();

    const int len = lens[c];

    if (tid < Q_RGN) {
        float mx = -1e30f;
        for (int l = 0; l < len; l++) mx = fmaxf(mx, sS[l][tid]);
        float sum = 0.f;
        for (int l = 0; l < len; l++) sum += expf(9.f * (sS[l][tid] - mx));
        float invs = 1.f / sum;
        for (int l = 0; l < L_MAX; l++) {
            float a = (l < len) ? expf(9.f * (sS[l][tid] - mx)) * invs : 0.f;
            sS[l][tid] = a;
        }
    }
    __syncthreads();

    size_t obase = ((size_t)(c * I_IMG + i)) * Q_RGN * D_EMB;
    for (int q = 0; q < Q_RGN; q++) {
        for (int d = tid; d < D_EMB; d += 256) {
            float a = 0.f;
            for (int l = 0; l < len; l++)
                a += sS[l][q] * wrdC[l * D_EMB + d];
            __half h, lo;
            split_h(a, h, lo);
            weiH[obase + q * D_EMB + d] = h;
            weiL[obase + q * D_EMB + d] = lo;
        }
    }
}

// ---------------------------------------------------------------------------
// weight split: fp32 -> fp16 hi/lo
// ---------------------------------------------------------------------------
__global__ __launch_bounds__(256) void split_kernel(
    const float* __restrict__ s, __half* __restrict__ h,
    __half* __restrict__ l, int n)
{
    int i = blockIdx.x * 256 + threadIdx.x;
    if (i < n) {
        __half hh, ll;
        split_h(s[i], hh, ll);
        h[i] = hh; l[i] = ll;
    }
}

// ---------------------------------------------------------------------------
// HMMA GEMM: D[m,n] = epi( sum_k A[m,k] * W[n,k] + bias[n] )
// fp16x2 compensated (Ah*Bh + Ah*Bl + Al*Bh), fp32 accum.
// 128x128x32 tiles, 3-stage cp.async pipeline, mma.m16n8k16.
// ---------------------------------------------------------------------------
#define EPI_TANH 0
#define EPI_FILM 1
#define EPI_RELU 2
#define EPI_FINAL 3

#define BK 32
#define TILE_B 8192                 // 128 rows x 64 bytes
#define STAGE_B (4 * TILE_B)        // Ah, Al, Bh, Bl
#define NSTAGE 3
#define SMEM_DYN (NSTAGE * STAGE_B) // 96 KB
#define NITER (D_EMB / BK)          // 32

__device__ __forceinline__ uint32_t smem_u32(const void* p) {
    uint32_t a;
    asm("{ .reg .u64 t; cvta.to.shared.u64 t, %1; cvt.u32.u64 %0, t; }"
        : "=r"(a) : "l"(p));
    return a;
}
__device__ __forceinline__ uint32_t sm_addr(uint32_t base, int row, int c16) {
    return base + row * 64 + (((uint32_t)(c16 ^ ((row >> 1) & 3))) << 4);
}
__device__ __forceinline__ void load_tile(
    const __half* __restrict__ g, int row0, int kcol0, uint32_t sb, int tid)
{
#pragma unroll
    for (int j = 0; j < 2; j++) {
        int id = tid + 256 * j;        // 0..511
        int r = id >> 2, c = id & 3;
        const void* gp = g + (size_t)(row0 + r) * D_EMB + kcol0 + c * 8;
        uint32_t sa = sm_addr(sb, r, c);
        asm volatile("cp.async.cg.shared.global [%0], [%1], 16;" :: "r"(sa), "l"(gp));
    }
}

#define LDSM_X4(R, addr) \
    asm volatile("ldmatrix.sync.aligned.m8n8.x4.shared.b16 {%0,%1,%2,%3}, [%4];" \
        : "=r"((R)[0]), "=r"((R)[1]), "=r"((R)[2]), "=r"((R)[3]) : "r"(addr))
#define MMA(C, A, B) \
    asm volatile("mma.sync.aligned.m16n8k16.row.col.f32.f16.f16.f32 " \
        "{%0,%1,%2,%3}, {%4,%5,%6,%7}, {%8,%9}, {%0,%1,%2,%3};" \
        : "+f"((C)[0]), "+f"((C)[1]), "+f"((C)[2]), "+f"((C)[3]) \
        : "r"((A)[0]), "r"((A)[1]), "r"((A)[2]), "r"((A)[3]), "r"((B)[0]), "r"((B)[1]))

template <int EPI>
__global__ __launch_bounds__(256, 1) void gemm_hmma(
    const __half* __restrict__ Ah, const __half* __restrict__ Al,
    const __half* __restrict__ Bh, const __half* __restrict__ Bl,
    const float* __restrict__ bias,
    const float* __restrict__ scal,      // FILM
    const float* __restrict__ rgn,       // FILM / FINAL
    float* __restrict__ outF,
    __half* __restrict__ outH, __half* __restrict__ outL)
{
    extern __shared__ __align__(1024) uint8_t dsm[];
    const uint32_t sb = smem_u32(dsm);

    const int tid = threadIdx.x;
    const int wid = tid >> 5;
    const int lid = tid & 31;
    const int wm = wid & 3;        // 4 warps along M
    const int wn = wid >> 2;       // 2 warps along N
    const int m0 = blockIdx.y * 128;
    const int n0 = blockIdx.x * 128;

    // ldmatrix lane address patterns
    const int a_ro = lid & 15;            // A: lanes 0-15 rows, 16-31 col+8
    const int a_co = lid >> 4;
    const int b_ro = ((lid >> 4) & 1) * 8 + (lid & 7);  // B (non-trans):
    const int b_co = (lid >> 3) & 1;                     // m0:n0-7/k0-7, m1:n0-7/k8-15,
                                                         // m2:n8-15/k0-7, m3:n8-15/k8-15
    float c[2][8][4];
#pragma unroll
    for (int a = 0; a < 2; a++)
#pragma unroll
        for (int b = 0; b < 8; b++)
#pragma unroll
            for (int d = 0; d < 4; d++) c[a][b][d] = 0.f;

    // prologue: stages 0, 1
#pragma unroll
    for (int s = 0; s < 2; s++) {
        uint32_t st = sb + s * STAGE_B;
        load_tile(Ah, m0, s * BK, st + 0 * TILE_B, tid);
        load_tile(Al, m0, s * BK, st + 1 * TILE_B, tid);
        load_tile(Bh, n0, s * BK, st + 2 * TILE_B, tid);
        load_tile(Bl, n0, s * BK, st + 3 * TILE_B, tid);
        asm volatile("cp.async.commit_group;");
    }

    int stage = 0;
    for (int i = 0; i < NITER; i++) {
        asm volatile("cp.async.wait_group 1;");
        __syncthreads();

        if (i + 2 < NITER) {
            uint32_t st = sb + ((stage + 2) % NSTAGE) * STAGE_B;
            int kc = (i + 2) * BK;
            load_tile(Ah, m0, kc, st + 0 * TILE_B, tid);
            load_tile(Al, m0, kc, st + 1 * TILE_B, tid);
            load_tile(Bh, n0, kc, st + 2 * TILE_B, tid);
            load_tile(Bl, n0, kc, st + 3 * TILE_B, tid);
        }
        asm volatile("cp.async.commit_group;");

        uint32_t stA = sb + stage * STAGE_B;
#pragma unroll
        for (int ks = 0; ks < 2; ks++) {
            uint32_t aH[2][4], aL[2][4], bH[8][2], bL[8][2];
#pragma unroll
            for (int mi = 0; mi < 2; mi++) {
                LDSM_X4(aH[mi], sm_addr(stA + 0 * TILE_B, wm * 32 + mi * 16 + a_ro, ks * 2 + a_co));
                LDSM_X4(aL[mi], sm_addr(stA + 1 * TILE_B, wm * 32 + mi * 16 + a_ro, ks * 2 + a_co));
            }
#pragma unroll
            for (int p = 0; p < 4; p++) {
                uint32_t r[4];
                LDSM_X4(r, sm_addr(stA + 2 * TILE_B, wn * 64 + p * 16 + b_ro, ks * 2 + b_co));
                bH[2 * p][0] = r[0]; bH[2 * p][1] = r[1];
                bH[2 * p + 1][0] = r[2]; bH[2 * p + 1][1] = r[3];
                LDSM_X4(r, sm_addr(stA + 3 * TILE_B, wn * 64 + p * 16 + b_ro, ks * 2 + b_co));
                bL[2 * p][0] = r[0]; bL[2 * p][1] = r[1];
                bL[2 * p + 1][0] = r[2]; bL[2 * p + 1][1] = r[3];
            }
#pragma unroll
            for (int mi = 0; mi < 2; mi++)
#pragma unroll
                for (int nj = 0; nj < 8; nj++) {
                    MMA(c[mi][nj], aH[mi], bH[nj]);
                    MMA(c[mi][nj], aH[mi], bL[nj]);
                    MMA(c[mi][nj], aL[mi], bH[nj]);
                }
        }
        stage = (stage + 1) % NSTAGE;
    }

    // ---------------- epilogue ----------------
    const int nbase = n0 + wn * 64;
    const int mbase = m0 + wm * 32;
    const int cph = (lid & 3) * 2;

    float2 bv[8];
#pragma unroll
    for (int nj = 0; nj < 8; nj++)
        bv[nj] = *(const float2*)(bias + nbase + nj * 8 + cph);

#pragma unroll
    for (int mi = 0; mi < 2; mi++) {
#pragma unroll
        for (int hf = 0; hf < 2; hf++) {
            const int m = mbase + mi * 16 + hf * 8 + (lid >> 2);
            const int t = m / Q_RGN;
            const int q = m - t * Q_RGN;
            const int i_img = t & (I_IMG - 1);
            const int cc = t >> 5;

            if (EPI == EPI_TANH) {
                float* op = outF + (size_t)m * D_EMB + nbase + cph;
#pragma unroll
                for (int nj = 0; nj < 8; nj++) {
                    float2 o;
                    o.x = tanhf(c[mi][nj][hf * 2 + 0] + bv[nj].x);
                    o.y = tanhf(c[mi][nj][hf * 2 + 1] + bv[nj].y);
                    *(float2*)(op + nj * 8) = o;
                }
            } else if (EPI == EPI_FILM) {
                const float* rp = rgn + ((size_t)(i_img * Q_RGN + q)) * D_EMB + nbase + cph;
                const float* sp = scal + (size_t)m * D_EMB + nbase + cph;
                size_t ob = (size_t)m * D_EMB + nbase + cph;
#pragma unroll
                for (int nj = 0; nj < 8; nj++) {
                    float2 rv = *(const float2*)(rp + nj * 8);
                    float2 sv = *(const float2*)(sp + nj * 8);
                    float x0 = rv.x * sv.x + (c[mi][nj][hf * 2 + 0] + bv[nj].x);
                    float x1 = rv.y * sv.y + (c[mi][nj][hf * 2 + 1] + bv[nj].y);
                    __half h0, l0, h1, l1;
                    split_h(x0, h0, l0); split_h(x1, h1, l1);
                    *(__half2*)(outH + ob + nj * 8) = __halves2half2(h0, h1);
                    *(__half2*)(outL + ob + nj * 8) = __halves2half2(l0, l1);
                }
            } else if (EPI == EPI_RELU) {
                size_t ob = (size_t)m * D_EMB + nbase + cph;
#pragma unroll
                for (int nj = 0; nj < 8; nj++) {
                    float x0 = fmaxf(c[mi][nj][hf * 2 + 0] + bv[nj].x, 0.f);
                    float x1 = fmaxf(c[mi][nj][hf * 2 + 1] + bv[nj].y, 0.f);
                    __half h0, l0, h1, l1;
                    split_h(x0, h0, l0); split_h(x1, h1, l1);
                    *(__half2*)(outH + ob + nj * 8) = __halves2half2(h0, h1);
                    *(__half2*)(outL + ob + nj * 8) = __halves2half2(l0, l1);
                }
            } else {  // EPI_FINAL
                const float* rp = rgn + ((size_t)(i_img * Q_RGN + q)) * D_EMB + nbase + cph;
                float* op = outF + (((size_t)(i_img * C_CAP + cc)) * Q_RGN + q) * D_EMB + nbase + cph;
#pragma unroll
                for (int nj = 0; nj < 8; nj++) {
                    float2 rv = *(const float2*)(rp + nj * 8);
                    float2 o;
                    o.x = c[mi][nj][hf * 2 + 0] + bv[nj].x + rv.x;
                    o.y = c[mi][nj][hf * 2 + 1] + bv[nj].y + rv.y;
                    *(float2*)(op + nj * 8) = o;
                }
            }
        }
    }
}

// ---------------------------------------------------------------------------
extern "C" void kernel_launch(void* const* d_in, const int* in_sizes, int n_in,
                              void* d_out, int out_size)
{
    const float* rgn     = (const float*)d_in[0];
    const float* wrd     = (const float*)d_in[2];
    const int*   lens    = (const int*)d_in[4];
    const float* w_scale = (const float*)d_in[5];
    const float* b_scale = (const float*)d_in[6];
    const float* w_shift = (const float*)d_in[7];
    const float* b_shift = (const float*)d_in[8];
    const float* w1      = (const float*)d_in[9];
    const float* b1      = (const float*)d_in[10];
    const float* w2      = (const float*)d_in[11];
    const float* b2      = (const float*)d_in[12];
    float* out = (float*)d_out;

    __half *weiH, *weiL, *xH, *xL, *hH, *hL, *wH, *wL;
    float* scal;
    cudaGetSymbolAddress((void**)&weiH, g_weiH);
    cudaGetSymbolAddress((void**)&weiL, g_weiL);
    cudaGetSymbolAddress((void**)&xH,   g_xH);
    cudaGetSymbolAddress((void**)&xL,   g_xL);
    cudaGetSymbolAddress((void**)&hH,   g_hH);
    cudaGetSymbolAddress((void**)&hL,   g_hL);
    cudaGetSymbolAddress((void**)&scal, g_scal);
    cudaGetSymbolAddress((void**)&wH,   g_wH);
    cudaGetSymbolAddress((void**)&wL,   g_wL);

    cudaFuncSetAttribute(gemm_hmma<EPI_TANH>,  cudaFuncAttributeMaxDynamicSharedMemorySize, SMEM_DYN);
    cudaFuncSetAttribute(gemm_hmma<EPI_FILM>,  cudaFuncAttributeMaxDynamicSharedMemorySize, SMEM_DYN);
    cudaFuncSetAttribute(gemm_hmma<EPI_RELU>,  cudaFuncAttributeMaxDynamicSharedMemorySize, SMEM_DYN);
    cudaFuncSetAttribute(gemm_hmma<EPI_FINAL>, cudaFuncAttributeMaxDynamicSharedMemorySize, SMEM_DYN);

    // K1: attention + weighted context -> wei hi/lo
    attn_wei_kernel<<<dim3(I_IMG, C_CAP), 256>>>(rgn, wrd, lens, weiH, weiL);

    // weight splits (tiny)
    const float* ws[4] = { w_scale, w_shift, w1, w2 };
    for (int k = 0; k < 4; k++)
        split_kernel<<<(W_ELEMS + 255) / 256, 256>>>(ws[k], wH + (size_t)k * W_ELEMS,
                                                     wL + (size_t)k * W_ELEMS, W_ELEMS);

    dim3 ggrid(D_EMB / 128, M_TOT / 128);   // (8, 288): x-adjacent CTAs share A tile in L2

    // G2: scaling = tanh(wei @ w_scale^T + b_scale) -> scal (fp32)
    gemm_hmma<EPI_TANH><<<ggrid, 256, SMEM_DYN>>>(
        weiH, weiL, wH + 0 * (size_t)W_ELEMS, wL + 0 * (size_t)W_ELEMS,
        b_scale, nullptr, nullptr, scal, nullptr, nullptr);
    // G3+film: x = rgn*scal + (wei @ w_shift^T + b_shift) -> x hi/lo
    gemm_hmma<EPI_FILM><<<ggrid, 256, SMEM_DYN>>>(
        weiH, weiL, wH + 1 * (size_t)W_ELEMS, wL + 1 * (size_t)W_ELEMS,
        b_shift, scal, rgn, nullptr, xH, xL);
    // G5: h = relu(x @ w1^T + b1) -> h hi/lo
    gemm_hmma<EPI_RELU><<<ggrid, 256, SMEM_DYN>>>(
        xH, xL, wH + 2 * (size_t)W_ELEMS, wL + 2 * (size_t)W_ELEMS,
        b1, nullptr, nullptr, nullptr, hH, hL);
    // G6: out = (h @ w2^T + b2) + rgn, transposed (c,i)->(i,c)
    gemm_hmma<EPI_FINAL><<<ggrid, 256, SMEM_DYN>>>(
        hH, hL, wH + 3 * (size_t)W_ELEMS, wL + 3 * (size_t)W_ELEMS,
        b2, nullptr, rgn, out, nullptr, nullptr);
}